// round 8
// baseline (speedup 1.0000x reference)
#include <cuda_runtime.h>
#include <cuda_bf16.h>

#define NBLOCKS 2048
#define NTHREADS 256

__device__ float g_partials[NBLOCKS];
__device__ int   g_ticket = 0;   // reset to 0 by the last block each call

__device__ __forceinline__ float ex2f(float x) {
    float y; asm("ex2.approx.ftz.f32 %0, %1;" : "=f"(y) : "f"(x)); return y;
}
__device__ __forceinline__ float lg2f(float x) {
    float y; asm("lg2.approx.ftz.f32 %0, %1;" : "=f"(y) : "f"(x)); return y;
}
__device__ __forceinline__ float rcpf(float x) {
    float y; asm("rcp.approx.ftz.f32 %0, %1;" : "=f"(y) : "f"(x)); return y;
}

// Accumulate one sample into (log2-domain acc, linear acc).
// total per-thread loss = 0.5 * ( ln2 * accL - accR ).
__device__ __forceinline__ void sample_acc(float l0, float l1, float l2,
                                           float t0, float t1, float t2,
                                           int h, float conf,
                                           float& accL, float& accR) {
    const float L2E = 1.44269504088896f;
    // invT: conf>0.9 -> 1/1.5 ; conf>0.6 -> 1/2 ; else 1/min(3.7-2c,3) = max(rcp(3.7-2c), 1/3)
    float low_inv = fmaxf(rcpf(__fmaf_rn(-2.0f, conf, 3.7f)), 0.33333334f);
    float invT = (conf > 0.9f) ? 0.66666667f : ((conf > 0.6f) ? 0.5f : low_inv);

    float a = invT * L2E;
    // KL lse term (log2 domain): p = sum 2^(l*invT*log2e)
    float p = ex2f(l0 * a) + ex2f(l1 * a) + ex2f(l2 * a);
    // CE lse term (log2 domain): q = sum 2^(l*log2e)
    float q = ex2f(l0 * L2E) + ex2f(l1 * L2E) + ex2f(l2 * L2E);
    // sum t*log2(t)  (t > 0 always: normalized uniform + 1e-3)
    float tl = t0 * lg2f(t0);
    tl = __fmaf_rn(t1, lg2f(t1), tl);
    tl = __fmaf_rn(t2, lg2f(t2), tl);
    // sum t*l
    float td = t0 * l0;
    td = __fmaf_rn(t1, l1, td);
    td = __fmaf_rn(t2, l2, td);
    // hard-label logit
    float lh = (h == 0) ? l0 : ((h == 1) ? l1 : l2);

    accL += lg2f(p) + tl + lg2f(q);
    accR += __fmaf_rn(invT, td, lh);
}

__device__ __forceinline__ void group_acc(const float4* __restrict__ logits4,
                                          const int4*   __restrict__ hard4,
                                          const float4* __restrict__ soft4,
                                          const float4* __restrict__ conf4,
                                          int g, float& accL, float& accR) {
    const float4 L0 = logits4[3 * g + 0];
    const float4 L1 = logits4[3 * g + 1];
    const float4 L2 = logits4[3 * g + 2];
    const float4 S0 = soft4[3 * g + 0];
    const float4 S1 = soft4[3 * g + 1];
    const float4 S2 = soft4[3 * g + 2];
    const int4   H  = hard4[g];
    const float4 Cf = conf4[g];

    sample_acc(L0.x, L0.y, L0.z, S0.x, S0.y, S0.z, H.x, Cf.x, accL, accR);
    sample_acc(L0.w, L1.x, L1.y, S0.w, S1.x, S1.y, H.y, Cf.y, accL, accR);
    sample_acc(L1.z, L1.w, L2.x, S1.z, S1.w, S2.x, H.z, Cf.z, accL, accR);
    sample_acc(L2.y, L2.z, L2.w, S2.y, S2.z, S2.w, H.w, Cf.w, accL, accR);
}

__global__ void __launch_bounds__(NTHREADS, 6)
adl_fused_kernel(const float4* __restrict__ logits4,
                 const int4*   __restrict__ hard4,
                 const float4* __restrict__ soft4,
                 const float4* __restrict__ conf4,
                 int ngroups /* = B/4 */,
                 float* __restrict__ out,
                 float inv_n) {
    const int stride = gridDim.x * blockDim.x;
    const bool exact = (ngroups == 4 * stride);   // B = 2^23 case
    int g = blockIdx.x * blockDim.x + threadIdx.x;
    float accL = 0.0f, accR = 0.0f;

    if (exact) {
        #pragma unroll
        for (int it = 0; it < 4; ++it, g += stride)
            group_acc(logits4, hard4, soft4, conf4, g, accL, accR);
    } else {
        for (; g < ngroups; g += stride)
            group_acc(logits4, hard4, soft4, conf4, g, accL, accR);
    }

    // per-thread combine: 0.5 * (ln2*accL - accR)
    float acc = 0.5f * (0.69314718055995f * accL - accR);

    // block reduction: warp shuffle then shared
    __shared__ float warp_sums[NTHREADS / 32];
    #pragma unroll
    for (int off = 16; off > 0; off >>= 1)
        acc += __shfl_down_sync(0xFFFFFFFFu, acc, off);
    if ((threadIdx.x & 31) == 0)
        warp_sums[threadIdx.x >> 5] = acc;
    __syncthreads();

    __shared__ bool is_last;
    if (threadIdx.x == 0) {
        float v = 0.0f;
        #pragma unroll
        for (int w = 0; w < NTHREADS / 32; w++) v += warp_sums[w];
        g_partials[blockIdx.x] = v;
        __threadfence();
        int t = atomicAdd(&g_ticket, 1);
        is_last = (t == NBLOCKS - 1);
    }
    __syncthreads();

    if (is_last) {
        __threadfence();  // acquire side: observe all blocks' partials
        const volatile float* vp = g_partials;
        float facc = 0.0f;
        #pragma unroll
        for (int i = 0; i < NBLOCKS / NTHREADS; ++i)   // 8 fixed-order adds/thread
            facc += vp[i * NTHREADS + threadIdx.x];
        #pragma unroll
        for (int off = 16; off > 0; off >>= 1)
            facc += __shfl_down_sync(0xFFFFFFFFu, facc, off);
        if ((threadIdx.x & 31) == 0)
            warp_sums[threadIdx.x >> 5] = facc;
        __syncthreads();
        if (threadIdx.x == 0) {
            float s = 0.0f;
            #pragma unroll
            for (int w = 0; w < NTHREADS / 32; w++) s += warp_sums[w];
            out[0] = s * inv_n;      // inv_n = 2^-23: exact power-of-two scale
            g_ticket = 0;            // reset for next graph replay
        }
    }
}

extern "C" void kernel_launch(void* const* d_in, const int* in_sizes, int n_in,
                              void* d_out, int out_size) {
    // metadata order: logits (B*3 f32), hard_labels (B i32), soft_labels (B*3 f32), confidences (B f32)
    const float4* logits4 = (const float4*)d_in[0];
    const int4*   hard4   = (const int4*)d_in[1];
    const float4* soft4   = (const float4*)d_in[2];
    const float4* conf4   = (const float4*)d_in[3];
    const int n = in_sizes[1];          // B
    const int ngroups = n / 4;

    adl_fused_kernel<<<NBLOCKS, NTHREADS>>>(logits4, hard4, soft4, conf4,
                                            ngroups, (float*)d_out,
                                            1.0f / (float)n);
}

// round 10
// speedup vs baseline: 1.0018x; 1.0018x over previous
#include <cuda_runtime.h>
#include <cuda_bf16.h>

#define NSMS 148
#define NBLOCKS (NSMS * 6)   // 888: exactly one wave at 6 CTAs/SM
#define NTHREADS 256

__device__ float g_partials[NBLOCKS];
__device__ int   g_ticket = 0;   // reset to 0 by the last block each call

__device__ __forceinline__ float ex2f(float x) {
    float y; asm("ex2.approx.ftz.f32 %0, %1;" : "=f"(y) : "f"(x)); return y;
}
__device__ __forceinline__ float lg2f(float x) {
    float y; asm("lg2.approx.ftz.f32 %0, %1;" : "=f"(y) : "f"(x)); return y;
}
__device__ __forceinline__ float rcpf(float x) {
    float y; asm("rcp.approx.ftz.f32 %0, %1;" : "=f"(y) : "f"(x)); return y;
}

// Accumulate one sample into (log2-domain acc, linear acc).
// total per-thread loss = 0.5 * ( ln2 * accL - accR ).
__device__ __forceinline__ void sample_acc(float l0, float l1, float l2,
                                           float t0, float t1, float t2,
                                           int h, float conf,
                                           float& accL, float& accR) {
    const float L2E = 1.44269504088896f;
    // invT: conf>0.9 -> 1/1.5 ; conf>0.6 -> 1/2 ; else 1/min(3.7-2c,3) = max(rcp(3.7-2c), 1/3)
    float low_inv = fmaxf(rcpf(__fmaf_rn(-2.0f, conf, 3.7f)), 0.33333334f);
    float invT = (conf > 0.9f) ? 0.66666667f : ((conf > 0.6f) ? 0.5f : low_inv);

    float a = invT * L2E;
    float p = ex2f(l0 * a) + ex2f(l1 * a) + ex2f(l2 * a);        // KL lse (log2)
    float q = ex2f(l0 * L2E) + ex2f(l1 * L2E) + ex2f(l2 * L2E);  // CE lse (log2)
    float tl = t0 * lg2f(t0);                                    // sum t*log2 t
    tl = __fmaf_rn(t1, lg2f(t1), tl);
    tl = __fmaf_rn(t2, lg2f(t2), tl);
    float td = t0 * l0;                                          // sum t*l
    td = __fmaf_rn(t1, l1, td);
    td = __fmaf_rn(t2, l2, td);
    float lh = (h == 0) ? l0 : ((h == 1) ? l1 : l2);

    accL += lg2f(p) + tl + lg2f(q);
    accR += __fmaf_rn(invT, td, lh);
}

__device__ __forceinline__ void group_acc(const float4* __restrict__ logits4,
                                          const int4*   __restrict__ hard4,
                                          const float4* __restrict__ soft4,
                                          const float4* __restrict__ conf4,
                                          int g, float& accL, float& accR) {
    // streaming (evict-first) loads: data is read exactly once
    const float4 L0 = __ldcs(&logits4[3 * g + 0]);
    const float4 L1 = __ldcs(&logits4[3 * g + 1]);
    const float4 L2 = __ldcs(&logits4[3 * g + 2]);
    const float4 S0 = __ldcs(&soft4[3 * g + 0]);
    const float4 S1 = __ldcs(&soft4[3 * g + 1]);
    const float4 S2 = __ldcs(&soft4[3 * g + 2]);
    const int4   H  = __ldcs(&hard4[g]);
    const float4 Cf = __ldcs(&conf4[g]);

    sample_acc(L0.x, L0.y, L0.z, S0.x, S0.y, S0.z, H.x, Cf.x, accL, accR);
    sample_acc(L0.w, L1.x, L1.y, S0.w, S1.x, S1.y, H.y, Cf.y, accL, accR);
    sample_acc(L1.z, L1.w, L2.x, S1.z, S1.w, S2.x, H.z, Cf.z, accL, accR);
    sample_acc(L2.y, L2.z, L2.w, S2.y, S2.z, S2.w, H.w, Cf.w, accL, accR);
}

__global__ void __launch_bounds__(NTHREADS, 6)
adl_fused_kernel(const float4* __restrict__ logits4,
                 const int4*   __restrict__ hard4,
                 const float4* __restrict__ soft4,
                 const float4* __restrict__ conf4,
                 int ngroups /* = B/4 */,
                 float* __restrict__ out,
                 float inv_n) {
    const int stride = gridDim.x * blockDim.x;
    float accL = 0.0f, accR = 0.0f;

    // Persistent single-wave grid-stride loop (9-10 iters/thread at B=2^23).
    for (int g = blockIdx.x * blockDim.x + threadIdx.x; g < ngroups; g += stride)
        group_acc(logits4, hard4, soft4, conf4, g, accL, accR);

    // per-thread combine: 0.5 * (ln2*accL - accR)
    float acc = 0.5f * (0.69314718055995f * accL - accR);

    // block reduction: warp shuffle then shared
    __shared__ float warp_sums[NTHREADS / 32];
    #pragma unroll
    for (int off = 16; off > 0; off >>= 1)
        acc += __shfl_down_sync(0xFFFFFFFFu, acc, off);
    if ((threadIdx.x & 31) == 0)
        warp_sums[threadIdx.x >> 5] = acc;
    __syncthreads();

    __shared__ bool is_last;
    if (threadIdx.x == 0) {
        float v = 0.0f;
        #pragma unroll
        for (int w = 0; w < NTHREADS / 32; w++) v += warp_sums[w];
        g_partials[blockIdx.x] = v;
        __threadfence();
        int t = atomicAdd(&g_ticket, 1);
        is_last = (t == NBLOCKS - 1);
    }
    __syncthreads();

    if (is_last) {
        __threadfence();  // acquire side: observe all blocks' partials
        const volatile float* vp = g_partials;
        float facc = 0.0f;
        for (int i = threadIdx.x; i < NBLOCKS; i += NTHREADS)  // fixed-order
            facc += vp[i];
        #pragma unroll
        for (int off = 16; off > 0; off >>= 1)
            facc += __shfl_down_sync(0xFFFFFFFFu, facc, off);
        if ((threadIdx.x & 31) == 0)
            warp_sums[threadIdx.x >> 5] = facc;
        __syncthreads();
        if (threadIdx.x == 0) {
            float s = 0.0f;
            #pragma unroll
            for (int w = 0; w < NTHREADS / 32; w++) s += warp_sums[w];
            out[0] = s * inv_n;
            g_ticket = 0;            // reset for next graph replay
        }
    }
}

extern "C" void kernel_launch(void* const* d_in, const int* in_sizes, int n_in,
                              void* d_out, int out_size) {
    // metadata order: logits (B*3 f32), hard_labels (B i32), soft_labels (B*3 f32), confidences (B f32)
    const float4* logits4 = (const float4*)d_in[0];
    const int4*   hard4   = (const int4*)d_in[1];
    const float4* soft4   = (const float4*)d_in[2];
    const float4* conf4   = (const float4*)d_in[3];
    const int n = in_sizes[1];          // B
    const int ngroups = n / 4;

    adl_fused_kernel<<<NBLOCKS, NTHREADS>>>(logits4, hard4, soft4, conf4,
                                            ngroups, (float*)d_out,
                                            1.0f / (float)n);
}

// round 12
// speedup vs baseline: 1.0645x; 1.0625x over previous
#include <cuda_runtime.h>
#include <cuda_bf16.h>

#define NBLOCKS 2048
#define NTHREADS 256
#define NWARPS (NTHREADS / 32)

__device__ float g_partials[NBLOCKS];
__device__ int   g_ticket = 0;   // reset to 0 by the last block each call

__device__ __forceinline__ float ex2f(float x) {
    float y; asm("ex2.approx.ftz.f32 %0, %1;" : "=f"(y) : "f"(x)); return y;
}
__device__ __forceinline__ float lg2f(float x) {
    float y; asm("lg2.approx.ftz.f32 %0, %1;" : "=f"(y) : "f"(x)); return y;
}
__device__ __forceinline__ float rcpf(float x) {
    float y; asm("rcp.approx.ftz.f32 %0, %1;" : "=f"(y) : "f"(x)); return y;
}

// loss contribution: accL (log2 domain), accR (linear); total = 0.5*(ln2*accL - accR)
__device__ __forceinline__ void sample_acc(float l0, float l1, float l2,
                                           float t0, float t1, float t2,
                                           int h, float conf,
                                           float& accL, float& accR) {
    const float L2E = 1.44269504088896f;
    float low_inv = fmaxf(rcpf(__fmaf_rn(-2.0f, conf, 3.7f)), 0.33333334f);
    float invT = (conf > 0.9f) ? 0.66666667f : ((conf > 0.6f) ? 0.5f : low_inv);

    float a = invT * L2E;
    float p = ex2f(l0 * a) + ex2f(l1 * a) + ex2f(l2 * a);        // KL lse (log2)
    float q = ex2f(l0 * L2E) + ex2f(l1 * L2E) + ex2f(l2 * L2E);  // CE lse (log2)
    float tl = t0 * lg2f(t0);
    tl = __fmaf_rn(t1, lg2f(t1), tl);
    tl = __fmaf_rn(t2, lg2f(t2), tl);
    float td = t0 * l0;
    td = __fmaf_rn(t1, l1, td);
    td = __fmaf_rn(t2, l2, td);
    float lh = (h == 0) ? l0 : ((h == 1) ? l1 : l2);

    accL += lg2f(p) + tl + lg2f(q);
    accR += __fmaf_rn(invT, td, lh);
}

__global__ void __launch_bounds__(NTHREADS, 6)
adl_fused_kernel(const float4* __restrict__ logits4,
                 const int4*   __restrict__ hard4,
                 const float4* __restrict__ soft4,
                 const float4* __restrict__ conf4,
                 int ngroups /* = B/4 */,
                 float* __restrict__ out,
                 float inv_n) {
    const int stride = gridDim.x * blockDim.x;            // threads = groups/iter
    const int lane = threadIdx.x & 31;
    const int warp = threadIdx.x >> 5;
    float accL = 0.0f, accR = 0.0f;

    // per-warp staging: [0..95] logits float4s, [96..191] soft float4s
    __shared__ float4 stage[NWARPS][192];

    const bool exact = (ngroups == 4 * stride);           // B = 2^23 case

    if (exact) {
        const int nwarps_total = stride >> 5;             // warps in grid
        int w = (blockIdx.x * NWARPS) + warp;             // global warp id
        #pragma unroll
        for (int it = 0; it < 4; ++it, w += nwarps_total) {
            const int gbase = w << 5;                     // 32 groups per warp
            // coalesced global loads (16B thread-stride -> 4 lines per LDG)
            const float4* Lp = logits4 + (size_t)gbase * 3;
            const float4* Sp = soft4   + (size_t)gbase * 3;
            float4 A0 = __ldcs(&Lp[lane]);
            float4 A1 = __ldcs(&Lp[32 + lane]);
            float4 A2 = __ldcs(&Lp[64 + lane]);
            float4 B0 = __ldcs(&Sp[lane]);
            float4 B1 = __ldcs(&Sp[32 + lane]);
            float4 B2 = __ldcs(&Sp[64 + lane]);
            const int4   H  = __ldcs(&hard4[gbase + lane]);
            const float4 Cf = __ldcs(&conf4[gbase + lane]);

            __syncwarp();                 // previous iter's reads complete
            stage[warp][lane]        = A0;
            stage[warp][32 + lane]   = A1;
            stage[warp][64 + lane]   = A2;
            stage[warp][96 + lane]   = B0;
            stage[warp][128 + lane]  = B1;
            stage[warp][160 + lane]  = B2;
            __syncwarp();                 // stores visible to all lanes

            // per-lane reads at 48B stride: conflict-free for LDS.128
            float4 L0 = stage[warp][lane * 3 + 0];
            float4 L1 = stage[warp][lane * 3 + 1];
            float4 L2 = stage[warp][lane * 3 + 2];
            float4 S0 = stage[warp][96 + lane * 3 + 0];
            float4 S1 = stage[warp][96 + lane * 3 + 1];
            float4 S2 = stage[warp][96 + lane * 3 + 2];

            sample_acc(L0.x, L0.y, L0.z, S0.x, S0.y, S0.z, H.x, Cf.x, accL, accR);
            sample_acc(L0.w, L1.x, L1.y, S0.w, S1.x, S1.y, H.y, Cf.y, accL, accR);
            sample_acc(L1.z, L1.w, L2.x, S1.z, S1.w, S2.x, H.z, Cf.z, accL, accR);
            sample_acc(L2.y, L2.z, L2.w, S2.y, S2.z, S2.w, H.w, Cf.w, accL, accR);
        }
    } else {
        // generic fallback (uncoalesced, correct for any size)
        for (int g = blockIdx.x * blockDim.x + threadIdx.x; g < ngroups; g += stride) {
            const float4 L0 = __ldcs(&logits4[3 * g + 0]);
            const float4 L1 = __ldcs(&logits4[3 * g + 1]);
            const float4 L2 = __ldcs(&logits4[3 * g + 2]);
            const float4 S0 = __ldcs(&soft4[3 * g + 0]);
            const float4 S1 = __ldcs(&soft4[3 * g + 1]);
            const float4 S2 = __ldcs(&soft4[3 * g + 2]);
            const int4   H  = __ldcs(&hard4[g]);
            const float4 Cf = __ldcs(&conf4[g]);
            sample_acc(L0.x, L0.y, L0.z, S0.x, S0.y, S0.z, H.x, Cf.x, accL, accR);
            sample_acc(L0.w, L1.x, L1.y, S0.w, S1.x, S1.y, H.y, Cf.y, accL, accR);
            sample_acc(L1.z, L1.w, L2.x, S1.z, S1.w, S2.x, H.z, Cf.z, accL, accR);
            sample_acc(L2.y, L2.z, L2.w, S2.y, S2.z, S2.w, H.w, Cf.w, accL, accR);
        }
    }

    float acc = 0.5f * (0.69314718055995f * accL - accR);

    __shared__ float warp_sums[NWARPS];
    #pragma unroll
    for (int off = 16; off > 0; off >>= 1)
        acc += __shfl_down_sync(0xFFFFFFFFu, acc, off);
    if (lane == 0) warp_sums[warp] = acc;
    __syncthreads();

    __shared__ bool is_last;
    if (threadIdx.x == 0) {
        float v = 0.0f;
        #pragma unroll
        for (int w2 = 0; w2 < NWARPS; w2++) v += warp_sums[w2];
        g_partials[blockIdx.x] = v;
        __threadfence();
        int t = atomicAdd(&g_ticket, 1);
        is_last = (t == NBLOCKS - 1);
    }
    __syncthreads();

    if (is_last) {
        __threadfence();
        const volatile float* vp = g_partials;
        float facc = 0.0f;
        for (int i = threadIdx.x; i < NBLOCKS; i += NTHREADS)
            facc += vp[i];
        #pragma unroll
        for (int off = 16; off > 0; off >>= 1)
            facc += __shfl_down_sync(0xFFFFFFFFu, facc, off);
        if (lane == 0) warp_sums[warp] = facc;
        __syncthreads();
        if (threadIdx.x == 0) {
            float s = 0.0f;
            #pragma unroll
            for (int w2 = 0; w2 < NWARPS; w2++) s += warp_sums[w2];
            out[0] = s * inv_n;
            g_ticket = 0;
        }
    }
}

extern "C" void kernel_launch(void* const* d_in, const int* in_sizes, int n_in,
                              void* d_out, int out_size) {
    // metadata order: logits (B*3 f32), hard_labels (B i32), soft_labels (B*3 f32), confidences (B f32)
    const float4* logits4 = (const float4*)d_in[0];
    const int4*   hard4   = (const int4*)d_in[1];
    const float4* soft4   = (const float4*)d_in[2];
    const float4* conf4   = (const float4*)d_in[3];
    const int n = in_sizes[1];          // B
    const int ngroups = n / 4;

    adl_fused_kernel<<<NBLOCKS, NTHREADS>>>(logits4, hard4, soft4, conf4,
                                            ngroups, (float*)d_out,
                                            1.0f / (float)n);
}

// round 13
// speedup vs baseline: 1.1217x; 1.0538x over previous
#include <cuda_runtime.h>
#include <cuda_bf16.h>
#include <cstdint>

#define NTHREADS 256
#define NWARPS (NTHREADS / 32)
#define GPS 256                      // groups per stage (== NTHREADS)
#define NBLOCKS (148 * 3)            // 444: single wave at 3 CTAs/SM (smem-limited)

// smem layout (dynamic): two 32KB stage buffers + barriers
#define BYTES_L   (GPS * 48)         // logits per stage  = 12288
#define BYTES_S   (GPS * 48)         // soft per stage    = 12288
#define BYTES_H   (GPS * 16)         // hard per stage    = 4096
#define BYTES_C   (GPS * 16)         // conf per stage    = 4096
#define BUF_BYTES (BYTES_L + BYTES_S + BYTES_H + BYTES_C)   // 32768
#define OFF_L 0
#define OFF_S (OFF_L + BYTES_L)
#define OFF_H (OFF_S + BYTES_S)
#define OFF_C (OFF_H + BYTES_H)
#define SMEM_MBAR (2 * BUF_BYTES)    // two 8-byte mbarriers
#define SMEM_TOTAL (SMEM_MBAR + 16)

__device__ float g_partials[NBLOCKS];
__device__ int   g_ticket = 0;

__device__ __forceinline__ float ex2f(float x) {
    float y; asm("ex2.approx.ftz.f32 %0, %1;" : "=f"(y) : "f"(x)); return y;
}
__device__ __forceinline__ float lg2f(float x) {
    float y; asm("lg2.approx.ftz.f32 %0, %1;" : "=f"(y) : "f"(x)); return y;
}
__device__ __forceinline__ float rcpf(float x) {
    float y; asm("rcp.approx.ftz.f32 %0, %1;" : "=f"(y) : "f"(x)); return y;
}
__device__ __forceinline__ uint32_t s2u(const void* p) {
    return (uint32_t)__cvta_generic_to_shared(p);
}
__device__ __forceinline__ void mbar_init(uint32_t mbar, uint32_t cnt) {
    asm volatile("mbarrier.init.shared.b64 [%0], %1;" :: "r"(mbar), "r"(cnt) : "memory");
}
__device__ __forceinline__ void mbar_expect_tx(uint32_t mbar, uint32_t bytes) {
    asm volatile("mbarrier.arrive.expect_tx.shared.b64 _, [%0], %1;"
                 :: "r"(mbar), "r"(bytes) : "memory");
}
__device__ __forceinline__ void bulk_g2s(uint32_t dst, const void* src,
                                         uint32_t bytes, uint32_t mbar) {
    asm volatile("cp.async.bulk.shared::cta.global.mbarrier::complete_tx::bytes "
                 "[%0], [%1], %2, [%3];"
                 :: "r"(dst), "l"(src), "r"(bytes), "r"(mbar) : "memory");
}
__device__ __forceinline__ void mbar_wait(uint32_t mbar, uint32_t parity) {
    uint32_t done;
    asm volatile(
        "{\n\t.reg .pred p;\n\t"
        "mbarrier.try_wait.parity.acquire.cta.shared::cta.b64 p, [%1], %2;\n\t"
        "selp.b32 %0, 1, 0, p;\n\t}"
        : "=r"(done) : "r"(mbar), "r"(parity) : "memory");
    if (!done) {
        asm volatile(
            "{\n\t.reg .pred P1;\n\t"
            "WAIT_LOOP_%=:\n\t"
            "mbarrier.try_wait.parity.acquire.cta.shared::cta.b64 P1, [%0], %1, 0x989680;\n\t"
            "@P1 bra.uni WAIT_DONE_%=;\n\t"
            "bra.uni WAIT_LOOP_%=;\n\t"
            "WAIT_DONE_%=:\n\t}"
            :: "r"(mbar), "r"(parity) : "memory");
    }
}

// loss contribution: accL (log2 domain), accR (linear); total = 0.5*(ln2*accL - accR)
__device__ __forceinline__ void sample_acc(float l0, float l1, float l2,
                                           float t0, float t1, float t2,
                                           int h, float conf,
                                           float& accL, float& accR) {
    const float L2E = 1.44269504088896f;
    float low_inv = fmaxf(rcpf(__fmaf_rn(-2.0f, conf, 3.7f)), 0.33333334f);
    float invT = (conf > 0.9f) ? 0.66666667f : ((conf > 0.6f) ? 0.5f : low_inv);

    float a = invT * L2E;
    float p = ex2f(l0 * a) + ex2f(l1 * a) + ex2f(l2 * a);        // KL lse (log2)
    float q = ex2f(l0 * L2E) + ex2f(l1 * L2E) + ex2f(l2 * L2E);  // CE lse (log2)
    float tl = t0 * lg2f(t0);
    tl = __fmaf_rn(t1, lg2f(t1), tl);
    tl = __fmaf_rn(t2, lg2f(t2), tl);
    float td = t0 * l0;
    td = __fmaf_rn(t1, l1, td);
    td = __fmaf_rn(t2, l2, td);
    float lh = (h == 0) ? l0 : ((h == 1) ? l1 : l2);

    accL += lg2f(p * q) + tl;          // lg2(p)+lg2(q) fused
    accR += __fmaf_rn(invT, td, lh);
}

__global__ void __launch_bounds__(NTHREADS, 3)
adl_bulk_kernel(const char* __restrict__ logits_c,
                const char* __restrict__ hard_c,
                const char* __restrict__ soft_c,
                const char* __restrict__ conf_c,
                int ngroups, float* __restrict__ out, float inv_n) {
    extern __shared__ char smem[];
    const uint32_t smem_u = s2u(smem);
    const int tid = threadIdx.x;
    const int lane = tid & 31;
    const int warp = tid >> 5;
    const int total_stages = (ngroups + GPS - 1) / GPS;

    if (tid == 0) {
        mbar_init(smem_u + SMEM_MBAR, 1);
        mbar_init(smem_u + SMEM_MBAR + 8, 1);
    }
    __syncthreads();

    // prefetch helper inline: issue stage sid into buffer b (thread 0 only)
    auto prefetch = [&](int sid, int b) {
        const int gbase = sid * GPS;
        const int cnt = min(GPS, ngroups - gbase);
        const uint32_t bl = (uint32_t)cnt * 48;
        const uint32_t bh = (uint32_t)cnt * 16;
        const uint32_t mbar = smem_u + SMEM_MBAR + b * 8;
        const uint32_t base = smem_u + b * BUF_BYTES;
        mbar_expect_tx(mbar, 2 * bl + 2 * bh);
        bulk_g2s(base + OFF_L, logits_c + (size_t)gbase * 48, bl, mbar);
        bulk_g2s(base + OFF_S, soft_c   + (size_t)gbase * 48, bl, mbar);
        bulk_g2s(base + OFF_H, hard_c   + (size_t)gbase * 16, bh, mbar);
        bulk_g2s(base + OFF_C, conf_c   + (size_t)gbase * 16, bh, mbar);
    };

    float accL = 0.0f, accR = 0.0f;
    int sid = blockIdx.x;
    if (tid == 0 && sid < total_stages) prefetch(sid, 0);

    int i = 0;
    for (; sid < total_stages; sid += NBLOCKS, ++i) {
        const int b = i & 1;
        const int nsid = sid + NBLOCKS;
        if (tid == 0 && nsid < total_stages) prefetch(nsid, (i + 1) & 1);

        mbar_wait(smem_u + SMEM_MBAR + b * 8, (i >> 1) & 1);

        const int cnt = min(GPS, ngroups - sid * GPS);
        if (tid < cnt) {
            const char* base = smem + b * BUF_BYTES;
            const float4* Lp = (const float4*)(base + OFF_L) + tid * 3;
            const float4* Sp = (const float4*)(base + OFF_S) + tid * 3;
            const float4 L0 = Lp[0], L1 = Lp[1], L2 = Lp[2];
            const float4 S0 = Sp[0], S1 = Sp[1], S2 = Sp[2];
            const int4   H  = ((const int4*)(base + OFF_H))[tid];
            const float4 Cf = ((const float4*)(base + OFF_C))[tid];

            sample_acc(L0.x, L0.y, L0.z, S0.x, S0.y, S0.z, H.x, Cf.x, accL, accR);
            sample_acc(L0.w, L1.x, L1.y, S0.w, S1.x, S1.y, H.y, Cf.y, accL, accR);
            sample_acc(L1.z, L1.w, L2.x, S1.z, S1.w, S2.x, H.z, Cf.z, accL, accR);
            sample_acc(L2.y, L2.z, L2.w, S2.y, S2.z, S2.w, H.w, Cf.w, accL, accR);
        }
        __syncthreads();   // buffer b free for reuse
    }

    float acc = 0.5f * (0.69314718055995f * accL - accR);

    __shared__ float warp_sums[NWARPS];
    #pragma unroll
    for (int off = 16; off > 0; off >>= 1)
        acc += __shfl_down_sync(0xFFFFFFFFu, acc, off);
    if (lane == 0) warp_sums[warp] = acc;
    __syncthreads();

    __shared__ bool is_last;
    if (tid == 0) {
        float v = 0.0f;
        #pragma unroll
        for (int w = 0; w < NWARPS; w++) v += warp_sums[w];
        g_partials[blockIdx.x] = v;
        __threadfence();
        int t = atomicAdd(&g_ticket, 1);
        is_last = (t == NBLOCKS - 1);
    }
    __syncthreads();

    if (is_last) {
        __threadfence();
        const volatile float* vp = g_partials;
        float facc = 0.0f;
        for (int j = tid; j < NBLOCKS; j += NTHREADS)
            facc += vp[j];
        #pragma unroll
        for (int off = 16; off > 0; off >>= 1)
            facc += __shfl_down_sync(0xFFFFFFFFu, facc, off);
        if (lane == 0) warp_sums[warp] = facc;
        __syncthreads();
        if (tid == 0) {
            float s = 0.0f;
            #pragma unroll
            for (int w = 0; w < NWARPS; w++) s += warp_sums[w];
            out[0] = s * inv_n;
            g_ticket = 0;
        }
    }
}

extern "C" void kernel_launch(void* const* d_in, const int* in_sizes, int n_in,
                              void* d_out, int out_size) {
    // metadata order: logits (B*3 f32), hard_labels (B i32), soft_labels (B*3 f32), confidences (B f32)
    static bool attr_set = false;
    if (!attr_set) {
        cudaFuncSetAttribute(adl_bulk_kernel,
                             cudaFuncAttributeMaxDynamicSharedMemorySize, SMEM_TOTAL);
        attr_set = true;
    }
    const int n = in_sizes[1];          // B
    const int ngroups = n / 4;

    adl_bulk_kernel<<<NBLOCKS, NTHREADS, SMEM_TOTAL>>>(
        (const char*)d_in[0], (const char*)d_in[1],
        (const char*)d_in[2], (const char*)d_in[3],
        ngroups, (float*)d_out, 1.0f / (float)n);
}